// round 5
// baseline (speedup 1.0000x reference)
#include <cuda_runtime.h>
#include <cuda_bf16.h>
#include <cstdint>

// ============================================================================
// SelfAttention, mma.sync bf16x3-split, cp.async 3-stage pipeline.
// Round 5: 256-thr CTA (8 warps, warp tile 64x32), K-chunk 32 with hi|lo
// packed in one 128B smem row -> 32KB stages, 2 CTAs/SM for latency hiding.
//   s1..s4: split x, Wq, Wk, Wv -> bf16 hi/lo
//   k1: Qh/l = x@Wq^T+bq     k2: Kh/l = x@Wk^T+bk   k3: VTh/l = (x@Wv^T+bv)^T
//   k4: Sc(f32) = Q@K^T/32   k5: softmax -> Ph/l    k6: O = P@VT^T -> out
// ============================================================================

constexpr int S = 2048, D = 1024, NB = 4;
constexpr long SD  = (long)S * D;
constexpr long SSZ = (long)S * S;
constexpr long NX = (long)NB * S * D;
constexpr long NW = (long)D * D;
constexpr long NP = (long)NB * S * S;

constexpr long OXH = 0,        OXL = NX;
constexpr long OWQH = 2*NX,    OWQL = OWQH+NW, OWKH = OWQH+2*NW, OWKL = OWQH+3*NW,
               OWVH = OWQH+4*NW, OWVL = OWQH+5*NW;
constexpr long OQH = 2*NX+6*NW, OQL = OQH+NX, OKH = OQH+2*NX, OKL = OQH+3*NX,
               OVTH = OQH+4*NX, OVTL = OQH+5*NX;
constexpr long OPH = OQH+6*NX,  OPL = OPH+NP;
constexpr long NBF = OPL + NP;

__device__ __align__(128) __nv_bfloat16 g_bf[NBF];
__device__ float g_sc[NP];

// stage: A[128 rows x 128B (k0..31 hi | k0..31 lo)] + B same = 32KB
constexpr int STAGE  = 32 * 1024;
constexpr int OFF_A = 0, OFF_B = 16384;
constexpr int NSTG   = 3;
constexpr int SMEM_DYN = NSTG * STAGE + 1024;

#define SWZ(o) ((o) ^ (((o) >> 3) & 0x70))

// ---------------------------------------------------------------- helpers
__device__ __forceinline__ uint32_t smem_u32(const void* p) {
    uint32_t a;
    asm("{ .reg .u64 t; cvta.to.shared.u64 t, %1; cvt.u32.u64 %0, t; }"
        : "=r"(a) : "l"(p));
    return a;
}
__device__ __forceinline__ void ldsm4(uint32_t* r, uint32_t addr) {
    asm volatile("ldmatrix.sync.aligned.m8n8.x4.shared.b16 {%0,%1,%2,%3}, [%4];"
                 : "=r"(r[0]), "=r"(r[1]), "=r"(r[2]), "=r"(r[3]) : "r"(addr));
}
__device__ __forceinline__ void mma16816(float* d, const uint32_t* a,
                                         const uint32_t* b) {
    asm volatile(
        "mma.sync.aligned.m16n8k16.row.col.f32.bf16.bf16.f32 "
        "{%0,%1,%2,%3}, {%4,%5,%6,%7}, {%8,%9}, {%0,%1,%2,%3};"
        : "+f"(d[0]), "+f"(d[1]), "+f"(d[2]), "+f"(d[3])
        : "r"(a[0]), "r"(a[1]), "r"(a[2]), "r"(a[3]), "r"(b[0]), "r"(b[1]));
}
#define CPA16(dst, src) \
    asm volatile("cp.async.cg.shared.global [%0], [%1], 16;" \
                 :: "r"(dst), "l"(src) : "memory")
#define CP_COMMIT() asm volatile("cp.async.commit_group;" ::: "memory")

__device__ __forceinline__ void split2(float v0, float v1,
                                       uint32_t& h, uint32_t& l) {
    __nv_bfloat16 h0 = __float2bfloat16_rn(v0), h1 = __float2bfloat16_rn(v1);
    __nv_bfloat162 hh(h0, h1);
    __nv_bfloat162 ll(__float2bfloat16_rn(v0 - __bfloat162float(h0)),
                      __float2bfloat16_rn(v1 - __bfloat162float(h1)));
    h = *reinterpret_cast<uint32_t*>(&hh);
    l = *reinterpret_cast<uint32_t*>(&ll);
}

// ---------------------------------------------------------------- split
__global__ void __launch_bounds__(256)
split_arr(const float* __restrict__ in, __nv_bfloat16* __restrict__ oh,
          __nv_bfloat16* __restrict__ ol, long n)
{
    long i = ((long)blockIdx.x * 256 + threadIdx.x) * 4;
    if (i >= n) return;
    float4 v = *reinterpret_cast<const float4*>(in + i);
    uint2 h, l;
    split2(v.x, v.y, h.x, l.x);
    split2(v.z, v.w, h.y, l.y);
    *reinterpret_cast<uint2*>(oh + i) = h;
    *reinterpret_cast<uint2*>(ol + i) = l;
}

// ---------------------------------------------------------------- GEMM
// C(128x128) = scale * A[M,K](hi/lo,K-major,lda) @ B[N,K](hi/lo,K-major,ldb)^T
// mode 0: fp32 Cf[r*ldc+c]; 1: bf16 pair Ch/Cl[r*ldc+c]; 2: transposed pair.
__global__ void __launch_bounds__(256, 2)
mma_gemm(const __nv_bfloat16* __restrict__ Ah, const __nv_bfloat16* __restrict__ Al,
         const __nv_bfloat16* __restrict__ Bh, const __nv_bfloat16* __restrict__ Bl,
         const float* __restrict__ bias, float* __restrict__ Cf,
         __nv_bfloat16* __restrict__ Ch, __nv_bfloat16* __restrict__ Cl,
         int K, int lda, int ldb, int ldc,
         long sA, long sB, long sC, float scale, int has_bias, int mode)
{
    const long zb = blockIdx.z;

    extern __shared__ char smem_raw[];
    const uint32_t rawb  = smem_u32(smem_raw);
    const uint32_t abase = (rawb + 1023) & ~1023u;

    const int tid = threadIdx.x, lane = tid & 31, wid = tid >> 5;
    const long row0 = (long)blockIdx.y * 128, col0 = (long)blockIdx.x * 128;

    // ---- cp.async loader: thread -> row r (0..127), hi(hl=0)/lo(hl=1) half
    const int r = tid >> 1, hl = tid & 1;
    const __nv_bfloat16* gA =
        (hl ? Al + sA * zb : Ah + sA * zb) + (row0 + r) * (long)lda;
    const __nv_bfloat16* gB =
        (hl ? Bl + sB * zb : Bh + sB * zb) + (col0 + r) * (long)ldb;
    uint32_t dA[4], dB[4];
#pragma unroll
    for (int q = 0; q < 4; q++) {
        const uint32_t o = SWZ((uint32_t)r * 128 + hl * 64 + q * 16);
        dA[q] = OFF_A + o;
        dB[q] = OFF_B + o;
    }

    // ---- fragment lane constants (8 warps; warp tile 64(m) x 32(n))
    const int mw = (wid >> 2) * 64, nw = (wid & 3) * 32;
    uint32_t a_row[4], a_swz[4];
#pragma unroll
    for (int i = 0; i < 4; i++) {
        const uint32_t rb = (uint32_t)(mw + 16 * i + (lane & 15)) * 128;
        a_row[i] = rb; a_swz[i] = (rb >> 3) & 0x70;
    }
    const uint32_t a_kl = (uint32_t)((lane >> 4) << 4);
    uint32_t b_row[2], b_swz[2];
#pragma unroll
    for (int p = 0; p < 2; p++) {
        const uint32_t rb =
            (uint32_t)(nw + 16 * p + (lane & 7) + ((lane & 16) >> 1)) * 128;
        b_row[p] = rb; b_swz[p] = (rb >> 3) & 0x70;
    }
    const uint32_t b_kl = (uint32_t)((lane & 8) << 1);

    float acc[64];
#pragma unroll
    for (int i = 0; i < 64; i++) acc[i] = 0.f;

    const int nch = K >> 5;

#define ISSUE(ch) do {                                                        \
        const uint32_t _sb = abase + (uint32_t)((ch) % NSTG) * STAGE;         \
        const long _k = (long)(ch) * 32;                                      \
        _Pragma("unroll")                                                     \
        for (int q = 0; q < 4; q++) {                                         \
            CPA16(_sb + dA[q], gA + _k + q * 8);                              \
            CPA16(_sb + dB[q], gB + _k + q * 8);                              \
        }                                                                     \
        CP_COMMIT();                                                          \
    } while (0)

    ISSUE(0);
    ISSUE(1);

    for (int ch = 0; ch < nch; ch++) {
        if (ch + 1 < nch)
            asm volatile("cp.async.wait_group 1;" ::: "memory");
        else
            asm volatile("cp.async.wait_group 0;" ::: "memory");
        __syncthreads();
        if (ch + 2 < nch) ISSUE(ch + 2);

        const uint32_t sb = abase + (uint32_t)(ch % NSTG) * STAGE;
#pragma unroll
        for (int ks = 0; ks < 2; ks++) {
            const uint32_t kb = ks * 32;                 // byte col of k-step
            uint32_t af[4][4], bh[8], bl[8];
#pragma unroll
            for (int i = 0; i < 4; i++)                  // A hi
                ldsm4(af[i], sb + OFF_A + a_row[i] + ((kb + a_kl) ^ a_swz[i]));
#pragma unroll
            for (int p = 0; p < 2; p++) {                // B hi + lo
                const uint32_t ko = kb + b_kl;
                ldsm4(&bh[4 * p], sb + OFF_B + b_row[p] + (ko ^ b_swz[p]));
                ldsm4(&bl[4 * p], sb + OFF_B + b_row[p] + ((ko + 64) ^ b_swz[p]));
            }
#pragma unroll
            for (int i = 0; i < 4; i++)
#pragma unroll
                for (int j = 0; j < 4; j++) {
                    mma16816(acc + (i * 4 + j) * 4, af[i], &bh[j * 2]);  // hi*hi
                    mma16816(acc + (i * 4 + j) * 4, af[i], &bl[j * 2]);  // hi*lo
                }
#pragma unroll
            for (int i = 0; i < 4; i++)                  // A lo (reuse regs)
                ldsm4(af[i], sb + OFF_A + a_row[i] + (((kb + 64) + a_kl) ^ a_swz[i]));
#pragma unroll
            for (int i = 0; i < 4; i++)
#pragma unroll
                for (int j = 0; j < 4; j++)
                    mma16816(acc + (i * 4 + j) * 4, af[i], &bh[j * 2]);  // lo*hi
        }
    }
#undef ISSUE

    // ---- epilogue
    float* Cfp = Cf ? Cf + sC * zb : nullptr;
    __nv_bfloat16* Chp = Ch ? Ch + sC * zb : nullptr;
    __nv_bfloat16* Clp = Cl ? Cl + sC * zb : nullptr;
    const int qr = lane >> 2, qc = lane & 3;
#pragma unroll
    for (int i = 0; i < 4; i++)
#pragma unroll
        for (int j = 0; j < 4; j++) {
            const float* d = acc + (i * 4 + j) * 4;
#pragma unroll
            for (int h = 0; h < 2; h++) {
                const long rr = row0 + mw + 16 * i + qr + 8 * h;
                const long cc = col0 + nw + 8 * j + 2 * qc;
                float v0 = d[2 * h + 0] * scale, v1 = d[2 * h + 1] * scale;
                if (has_bias) { v0 += bias[cc]; v1 += bias[cc + 1]; }
                if (mode == 0) {
                    *reinterpret_cast<float2*>(&Cfp[rr * (long)ldc + cc]) =
                        make_float2(v0, v1);
                } else if (mode == 1) {
                    uint32_t hh, ll;
                    split2(v0, v1, hh, ll);
                    *reinterpret_cast<uint32_t*>(&Chp[rr * (long)ldc + cc]) = hh;
                    *reinterpret_cast<uint32_t*>(&Clp[rr * (long)ldc + cc]) = ll;
                } else {
                    __nv_bfloat16 h0 = __float2bfloat16_rn(v0);
                    __nv_bfloat16 h1 = __float2bfloat16_rn(v1);
                    Chp[cc * (long)ldc + rr]       = h0;
                    Chp[(cc + 1) * (long)ldc + rr] = h1;
                    Clp[cc * (long)ldc + rr] =
                        __float2bfloat16_rn(v0 - __bfloat162float(h0));
                    Clp[(cc + 1) * (long)ldc + rr] =
                        __float2bfloat16_rn(v1 - __bfloat162float(h1));
                }
            }
        }
}

// ---------------------------------------------------------------- softmax
__global__ void __launch_bounds__(256)
softmax_rows(const float* __restrict__ sc, __nv_bfloat16* __restrict__ ph,
             __nv_bfloat16* __restrict__ pl)
{
    const long ro = (long)blockIdx.x * 2048;
    const float* p = sc + ro;
    __shared__ float red[256];
    const int t = threadIdx.x;

    float v[8];
    float m = -3.4e38f;
#pragma unroll
    for (int i = 0; i < 8; i++) { v[i] = p[t + (i << 8)]; m = fmaxf(m, v[i]); }
    red[t] = m;
    __syncthreads();
    for (int s = 128; s > 0; s >>= 1) {
        if (t < s) red[t] = fmaxf(red[t], red[t + s]);
        __syncthreads();
    }
    m = red[0];
    __syncthreads();

    float sum = 0.f;
#pragma unroll
    for (int i = 0; i < 8; i++) { v[i] = __expf(v[i] - m); sum += v[i]; }
    red[t] = sum;
    __syncthreads();
    for (int s = 128; s > 0; s >>= 1) {
        if (t < s) red[t] += red[t + s];
        __syncthreads();
    }
    const float inv = 1.f / red[0];
#pragma unroll
    for (int i = 0; i < 8; i++) {
        float pv = v[i] * inv;
        __nv_bfloat16 h = __float2bfloat16_rn(pv);
        ph[ro + t + (i << 8)] = h;
        pl[ro + t + (i << 8)] = __float2bfloat16_rn(pv - __bfloat162float(h));
    }
}

// ---------------------------------------------------------------- launch
extern "C" void kernel_launch(void* const* d_in, const int* in_sizes, int n_in,
                              void* d_out, int out_size)
{
    const float* x  = (const float*)d_in[0];
    const float* Wq = (const float*)d_in[1];
    const float* bq = (const float*)d_in[2];
    const float* Wk = (const float*)d_in[3];
    const float* bk = (const float*)d_in[4];
    const float* Wv = (const float*)d_in[5];
    const float* bv = (const float*)d_in[6];
    float* out = (float*)d_out;

    __nv_bfloat16* bf; float* scp;
    cudaGetSymbolAddress((void**)&bf, g_bf);
    cudaGetSymbolAddress((void**)&scp, g_sc);

    cudaFuncSetAttribute(mma_gemm, cudaFuncAttributeMaxDynamicSharedMemorySize,
                         SMEM_DYN);
    dim3 thr(256);

    split_arr<<<(int)(NX / 1024), 256>>>(x,  bf + OXH,  bf + OXL,  NX);
    split_arr<<<(int)(NW / 1024), 256>>>(Wq, bf + OWQH, bf + OWQL, NW);
    split_arr<<<(int)(NW / 1024), 256>>>(Wk, bf + OWKH, bf + OWKL, NW);
    split_arr<<<(int)(NW / 1024), 256>>>(Wv, bf + OWVH, bf + OWVL, NW);

    dim3 g_qk(D / 128, (NB * S) / 128, 1);
    mma_gemm<<<g_qk, thr, SMEM_DYN>>>(bf+OXH, bf+OXL, bf+OWQH, bf+OWQL, bq,
                                      nullptr, bf+OQH, bf+OQL,
                                      D, D, D, D, 0, 0, 0, 1.f, 1, 1);
    mma_gemm<<<g_qk, thr, SMEM_DYN>>>(bf+OXH, bf+OXL, bf+OWKH, bf+OWKL, bk,
                                      nullptr, bf+OKH, bf+OKL,
                                      D, D, D, D, 0, 0, 0, 1.f, 1, 1);

    dim3 g_v(D / 128, S / 128, NB);
    mma_gemm<<<g_v, thr, SMEM_DYN>>>(bf+OXH, bf+OXL, bf+OWVH, bf+OWVL, bv,
                                     nullptr, bf+OVTH, bf+OVTL,
                                     D, D, D, S, SD, 0, SD, 1.f, 1, 2);

    dim3 g_sc(S / 128, S / 128, NB);
    mma_gemm<<<g_sc, thr, SMEM_DYN>>>(bf+OQH, bf+OQL, bf+OKH, bf+OKL, nullptr,
                                      scp, nullptr, nullptr,
                                      D, D, D, S, SD, SD, SSZ, 0.03125f, 0, 0);

    softmax_rows<<<NB * S, 256>>>(scp, bf + OPH, bf + OPL);

    dim3 g_o(D / 128, S / 128, NB);
    mma_gemm<<<g_o, thr, SMEM_DYN>>>(bf+OPH, bf+OPL, bf+OVTH, bf+OVTL, nullptr,
                                     out, nullptr, nullptr,
                                     S, S, S, D, SSZ, SD, SD, 1.f, 0, 0);
}

// round 6
// speedup vs baseline: 1.5797x; 1.5797x over previous
#include <cuda_runtime.h>
#include <cuda_bf16.h>
#include <cstdint>

// ============================================================================
// SelfAttention, mma.sync bf16x3-split, cp.async 3-stage pipelined GEMMs.
// R6 = R4 (best: 1001us) + independent-chain MMA ordering + smem-staged
// transposed epilogue for VT. 512 thr/CTA, 128x128 tile, K-chunk 64.
// ============================================================================

constexpr int S = 2048, D = 1024, NB = 4;
constexpr long SD  = (long)S * D;
constexpr long SSZ = (long)S * S;
constexpr long NX = (long)NB * S * D;
constexpr long NW = (long)D * D;
constexpr long NP = (long)NB * S * S;

constexpr long OXH = 0,        OXL = NX;
constexpr long OWQH = 2*NX,    OWQL = OWQH+NW, OWKH = OWQH+2*NW, OWKL = OWQH+3*NW,
               OWVH = OWQH+4*NW, OWVL = OWQH+5*NW;
constexpr long OQH = 2*NX+6*NW, OQL = OQH+NX, OKH = OQH+2*NX, OKL = OQH+3*NX,
               OVTH = OQH+4*NX, OVTL = OQH+5*NX;
constexpr long OPH = OQH+6*NX,  OPL = OPH+NP;
constexpr long NBF = OPL + NP;

__device__ __align__(128) __nv_bfloat16 g_bf[NBF];
__device__ float g_sc[NP];

constexpr int STAGE  = 64 * 1024;          // AH|AL|BH|BL x 16KB
constexpr int OFF_AH = 0, OFF_AL = 16384, OFF_BH = 32768, OFF_BL = 49152;
constexpr int NSTG   = 3;
constexpr int SMEM_DYN = NSTG * STAGE + 1024;

#define SWZ(o) ((o) ^ (((o) >> 3) & 0x70))

// ---------------------------------------------------------------- helpers
__device__ __forceinline__ uint32_t smem_u32(const void* p) {
    uint32_t a;
    asm("{ .reg .u64 t; cvta.to.shared.u64 t, %1; cvt.u32.u64 %0, t; }"
        : "=r"(a) : "l"(p));
    return a;
}
__device__ __forceinline__ void ldsm4(uint32_t* r, uint32_t addr) {
    asm volatile("ldmatrix.sync.aligned.m8n8.x4.shared.b16 {%0,%1,%2,%3}, [%4];"
                 : "=r"(r[0]), "=r"(r[1]), "=r"(r[2]), "=r"(r[3]) : "r"(addr));
}
__device__ __forceinline__ void mma16816(float* d, const uint32_t* a,
                                         const uint32_t* b) {
    asm volatile(
        "mma.sync.aligned.m16n8k16.row.col.f32.bf16.bf16.f32 "
        "{%0,%1,%2,%3}, {%4,%5,%6,%7}, {%8,%9}, {%0,%1,%2,%3};"
        : "+f"(d[0]), "+f"(d[1]), "+f"(d[2]), "+f"(d[3])
        : "r"(a[0]), "r"(a[1]), "r"(a[2]), "r"(a[3]), "r"(b[0]), "r"(b[1]));
}
#define CPA16(dst, src) \
    asm volatile("cp.async.cg.shared.global [%0], [%1], 16;" \
                 :: "r"(dst), "l"(src) : "memory")
#define CP_COMMIT() asm volatile("cp.async.commit_group;" ::: "memory")

__device__ __forceinline__ void split2(float v0, float v1,
                                       uint32_t& h, uint32_t& l) {
    __nv_bfloat16 h0 = __float2bfloat16_rn(v0), h1 = __float2bfloat16_rn(v1);
    __nv_bfloat162 hh(h0, h1);
    __nv_bfloat162 ll(__float2bfloat16_rn(v0 - __bfloat162float(h0)),
                      __float2bfloat16_rn(v1 - __bfloat162float(h1)));
    h = *reinterpret_cast<uint32_t*>(&hh);
    l = *reinterpret_cast<uint32_t*>(&ll);
}

// ---------------------------------------------------------------- split
__global__ void __launch_bounds__(256)
split_arr(const float* __restrict__ in, __nv_bfloat16* __restrict__ oh,
          __nv_bfloat16* __restrict__ ol, long n)
{
    long i = ((long)blockIdx.x * 256 + threadIdx.x) * 4;
    if (i >= n) return;
    float4 v = *reinterpret_cast<const float4*>(in + i);
    uint2 h, l;
    split2(v.x, v.y, h.x, l.x);
    split2(v.z, v.w, h.y, l.y);
    *reinterpret_cast<uint2*>(oh + i) = h;
    *reinterpret_cast<uint2*>(ol + i) = l;
}

// ---------------------------------------------------------------- GEMM
// C(128x128) = scale * A[M,K](hi/lo,K-major,lda) @ B[N,K](hi/lo,K-major,ldb)^T
// mode 0: fp32 Cf[r*ldc+c]; 1: bf16 pair Ch/Cl[r*ldc+c]; 2: transposed pair.
__global__ void __launch_bounds__(512, 1)
mma_gemm(const __nv_bfloat16* __restrict__ Ah, const __nv_bfloat16* __restrict__ Al,
         const __nv_bfloat16* __restrict__ Bh, const __nv_bfloat16* __restrict__ Bl,
         const float* __restrict__ bias, float* __restrict__ Cf,
         __nv_bfloat16* __restrict__ Ch, __nv_bfloat16* __restrict__ Cl,
         int K, int lda, int ldb, int ldc,
         long sA, long sB, long sC, float scale, int has_bias, int mode)
{
    const long zb = blockIdx.z;
    Ah += sA * zb; Al += sA * zb; Bh += sB * zb; Bl += sB * zb;

    extern __shared__ char smem_raw[];
    const uint32_t rawb  = smem_u32(smem_raw);
    const uint32_t abase = (rawb + 1023) & ~1023u;
    char* smem = smem_raw + (abase - rawb);

    const int tid = threadIdx.x, lane = tid & 31, wid = tid >> 5;
    const long row0 = (long)blockIdx.y * 128, col0 = (long)blockIdx.x * 128;

    // ---- cp.async loader mapping: r0 = row (0..63)[+64], s0 = 16B seg (0..7)
    const int r0 = tid >> 3, s0 = tid & 7;
    const uint32_t w0 = SWZ((uint32_t)r0 * 128 + s0 * 16);
    const uint32_t w1 = SWZ((uint32_t)(r0 + 64) * 128 + s0 * 16);
    const __nv_bfloat16* ga[8] = {
        Ah + (row0 + r0) * (long)lda + s0 * 8,
        Ah + (row0 + r0 + 64) * (long)lda + s0 * 8,
        Al + (row0 + r0) * (long)lda + s0 * 8,
        Al + (row0 + r0 + 64) * (long)lda + s0 * 8,
        Bh + (col0 + r0) * (long)ldb + s0 * 8,
        Bh + (col0 + r0 + 64) * (long)ldb + s0 * 8,
        Bl + (col0 + r0) * (long)ldb + s0 * 8,
        Bl + (col0 + r0 + 64) * (long)ldb + s0 * 8 };
    const uint32_t soff[8] = { OFF_AH + w0, OFF_AH + w1, OFF_AL + w0, OFF_AL + w1,
                               OFF_BH + w0, OFF_BH + w1, OFF_BL + w0, OFF_BL + w1 };

    // ---- fragment lane constants (warp 32x32 at (mw,nw))
    const int mw = (wid >> 2) * 32, nw = (wid & 3) * 32;
    uint32_t a_row[2], a_swz[2];
#pragma unroll
    for (int i = 0; i < 2; i++) {
        uint32_t rb = (uint32_t)(mw + 16 * i + (lane & 15)) * 128;
        a_row[i] = rb; a_swz[i] = (rb >> 3) & 0x70;
    }
    const uint32_t a_kl = (uint32_t)((lane >> 4) << 4);
    uint32_t b_row[2], b_swz[2];
#pragma unroll
    for (int p = 0; p < 2; p++) {
        uint32_t rb = (uint32_t)(nw + 16 * p + (lane & 7) + ((lane & 16) >> 1)) * 128;
        b_row[p] = rb; b_swz[p] = (rb >> 3) & 0x70;
    }
    const uint32_t b_kl = (uint32_t)((lane & 8) << 1);

    float acc[32];
#pragma unroll
    for (int i = 0; i < 32; i++) acc[i] = 0.f;

    const int nch = K >> 6;

#define ISSUE(ch) do {                                                        \
        const uint32_t _sb = abase + (uint32_t)((ch) % NSTG) * STAGE;         \
        const long _k = (long)(ch) * 64;                                      \
        _Pragma("unroll")                                                     \
        for (int q = 0; q < 8; q++) CPA16(_sb + soff[q], ga[q] + _k);         \
        CP_COMMIT();                                                          \
    } while (0)

    ISSUE(0);
    ISSUE(1);

    for (int ch = 0; ch < nch; ch++) {
        if (ch + 1 < nch)
            asm volatile("cp.async.wait_group 1;" ::: "memory");
        else
            asm volatile("cp.async.wait_group 0;" ::: "memory");
        __syncthreads();
        if (ch + 2 < nch) ISSUE(ch + 2);

        const uint32_t sb = abase + (uint32_t)(ch % NSTG) * STAGE;
#pragma unroll
        for (int ks = 0; ks < 4; ks++) {
            const uint32_t KB = ks * 32;
            uint32_t af[2][4], bh[8], bl[8];
#pragma unroll
            for (int i = 0; i < 2; i++)
                ldsm4(af[i], sb + OFF_AH + a_row[i] + ((KB + a_kl) ^ a_swz[i]));
#pragma unroll
            for (int p = 0; p < 2; p++) {
                const uint32_t ko = KB + b_kl;
                ldsm4(&bh[4 * p], sb + OFF_BH + b_row[p] + (ko ^ b_swz[p]));
                ldsm4(&bl[4 * p], sb + OFF_BL + b_row[p] + (ko ^ b_swz[p]));
            }
            // --- three batches of 8 independent MMAs (same-acc reuse dist 8)
#pragma unroll
            for (int i = 0; i < 2; i++)
#pragma unroll
                for (int j = 0; j < 4; j++)
                    mma16816(acc + (i * 4 + j) * 4, af[i], &bh[j * 2]);  // hi*hi
#pragma unroll
            for (int i = 0; i < 2; i++)
#pragma unroll
                for (int j = 0; j < 4; j++)
                    mma16816(acc + (i * 4 + j) * 4, af[i], &bl[j * 2]);  // hi*lo
#pragma unroll
            for (int i = 0; i < 2; i++)   // reload A as lo (reuse regs)
                ldsm4(af[i], sb + OFF_AL + a_row[i] + ((KB + a_kl) ^ a_swz[i]));
#pragma unroll
            for (int i = 0; i < 2; i++)
#pragma unroll
                for (int j = 0; j < 4; j++)
                    mma16816(acc + (i * 4 + j) * 4, af[i], &bh[j * 2]);  // lo*hi
        }
    }
#undef ISSUE

    // ---- epilogue
    float* Cfp = Cf ? Cf + sC * zb : nullptr;
    __nv_bfloat16* Chp = Ch ? Ch + sC * zb : nullptr;
    __nv_bfloat16* Clp = Cl ? Cl + sC * zb : nullptr;
    const int qr = lane >> 2, qc = lane & 3;

    if (mode == 2) {
        // stage transposed tile in smem (pipeline buffers are dead), then
        // coalesced 16B stores. planes: h at 0, l at 128*136 elems.
        __syncthreads();
        __nv_bfloat16* sh = reinterpret_cast<__nv_bfloat16*>(smem);
        __nv_bfloat16* sl = sh + 128 * 136;
#pragma unroll
        for (int i = 0; i < 2; i++)
#pragma unroll
            for (int j = 0; j < 4; j++) {
                const float* d = acc + (i * 4 + j) * 4;
#pragma unroll
                for (int h = 0; h < 2; h++) {
                    const int rl = mw + 16 * i + qr + 8 * h;
                    const int cl = nw + 8 * j + 2 * qc;
                    float v0 = d[2 * h + 0] * scale, v1 = d[2 * h + 1] * scale;
                    if (has_bias) { v0 += bias[col0 + cl]; v1 += bias[col0 + cl + 1]; }
                    __nv_bfloat16 h0 = __float2bfloat16_rn(v0);
                    __nv_bfloat16 h1 = __float2bfloat16_rn(v1);
                    sh[cl * 136 + rl]       = h0;
                    sh[(cl + 1) * 136 + rl] = h1;
                    sl[cl * 136 + rl] =
                        __float2bfloat16_rn(v0 - __bfloat162float(h0));
                    sl[(cl + 1) * 136 + rl] =
                        __float2bfloat16_rn(v1 - __bfloat162float(h1));
                }
            }
        __syncthreads();
        const int c = tid >> 2, seg = tid & 3;       // 128 rows x 4 segs of 64B
        const __nv_bfloat16* srh = sh + c * 136 + seg * 32;
        const __nv_bfloat16* srl = sl + c * 136 + seg * 32;
        __nv_bfloat16* dsh = Chp + (col0 + c) * (long)ldc + row0 + seg * 32;
        __nv_bfloat16* dsl = Clp + (col0 + c) * (long)ldc + row0 + seg * 32;
#pragma unroll
        for (int q = 0; q < 4; q++) {
            *reinterpret_cast<uint4*>(dsh + q * 8) =
                *reinterpret_cast<const uint4*>(srh + q * 8);
            *reinterpret_cast<uint4*>(dsl + q * 8) =
                *reinterpret_cast<const uint4*>(srl + q * 8);
        }
        return;
    }

#pragma unroll
    for (int i = 0; i < 2; i++)
#pragma unroll
        for (int j = 0; j < 4; j++) {
            const float* d = acc + (i * 4 + j) * 4;
#pragma unroll
            for (int h = 0; h < 2; h++) {
                const long r = row0 + mw + 16 * i + qr + 8 * h;
                const long c = col0 + nw + 8 * j + 2 * qc;
                float v0 = d[2 * h + 0] * scale, v1 = d[2 * h + 1] * scale;
                if (has_bias) { v0 += bias[c]; v1 += bias[c + 1]; }
                if (mode == 0) {
                    *reinterpret_cast<float2*>(&Cfp[r * (long)ldc + c]) =
                        make_float2(v0, v1);
                } else {
                    uint32_t hh, ll;
                    split2(v0, v1, hh, ll);
                    *reinterpret_cast<uint32_t*>(&Chp[r * (long)ldc + c]) = hh;
                    *reinterpret_cast<uint32_t*>(&Clp[r * (long)ldc + c]) = ll;
                }
            }
        }
}

// ---------------------------------------------------------------- softmax
__global__ void __launch_bounds__(256)
softmax_rows(const float* __restrict__ sc, __nv_bfloat16* __restrict__ ph,
             __nv_bfloat16* __restrict__ pl)
{
    const long ro = (long)blockIdx.x * 2048;
    const float* p = sc + ro;
    __shared__ float red[256];
    const int t = threadIdx.x;

    float v[8];
    float m = -3.4e38f;
#pragma unroll
    for (int i = 0; i < 8; i++) { v[i] = p[t + (i << 8)]; m = fmaxf(m, v[i]); }
    red[t] = m;
    __syncthreads();
    for (int s = 128; s > 0; s >>= 1) {
        if (t < s) red[t] = fmaxf(red[t], red[t + s]);
        __syncthreads();
    }
    m = red[0];
    __syncthreads();

    float sum = 0.f;
#pragma unroll
    for (int i = 0; i < 8; i++) { v[i] = __expf(v[i] - m); sum += v[i]; }
    red[t] = sum;
    __syncthreads();
    for (int s = 128; s > 0; s >>= 1) {
        if (t < s) red[t] += red[t + s];
        __syncthreads();
    }
    const float inv = 1.f / red[0];
#pragma unroll
    for (int i = 0; i < 8; i++) {
        float pv = v[i] * inv;
        __nv_bfloat16 h = __float2bfloat16_rn(pv);
        ph[ro + t + (i << 8)] = h;
        pl[ro + t + (i << 8)] = __float2bfloat16_rn(pv - __bfloat162float(h));
    }
}

// ---------------------------------------------------------------- launch
extern "C" void kernel_launch(void* const* d_in, const int* in_sizes, int n_in,
                              void* d_out, int out_size)
{
    const float* x  = (const float*)d_in[0];
    const float* Wq = (const float*)d_in[1];
    const float* bq = (const float*)d_in[2];
    const float* Wk = (const float*)d_in[3];
    const float* bk = (const float*)d_in[4];
    const float* Wv = (const float*)d_in[5];
    const float* bv = (const float*)d_in[6];
    float* out = (float*)d_out;

    __nv_bfloat16* bf; float* scp;
    cudaGetSymbolAddress((void**)&bf, g_bf);
    cudaGetSymbolAddress((void**)&scp, g_sc);

    cudaFuncSetAttribute(mma_gemm, cudaFuncAttributeMaxDynamicSharedMemorySize,
                         SMEM_DYN);
    dim3 thr(512);

    split_arr<<<(int)(NX / 1024), 256>>>(x,  bf + OXH,  bf + OXL,  NX);
    split_arr<<<(int)(NW / 1024), 256>>>(Wq, bf + OWQH, bf + OWQL, NW);
    split_arr<<<(int)(NW / 1024), 256>>>(Wk, bf + OWKH, bf + OWKL, NW);
    split_arr<<<(int)(NW / 1024), 256>>>(Wv, bf + OWVH, bf + OWVL, NW);

    dim3 g_qk(D / 128, (NB * S) / 128, 1);
    mma_gemm<<<g_qk, thr, SMEM_DYN>>>(bf+OXH, bf+OXL, bf+OWQH, bf+OWQL, bq,
                                      nullptr, bf+OQH, bf+OQL,
                                      D, D, D, D, 0, 0, 0, 1.f, 1, 1);
    mma_gemm<<<g_qk, thr, SMEM_DYN>>>(bf+OXH, bf+OXL, bf+OWKH, bf+OWKL, bk,
                                      nullptr, bf+OKH, bf+OKL,
                                      D, D, D, D, 0, 0, 0, 1.f, 1, 1);

    dim3 g_v(D / 128, S / 128, NB);
    mma_gemm<<<g_v, thr, SMEM_DYN>>>(bf+OXH, bf+OXL, bf+OWVH, bf+OWVL, bv,
                                     nullptr, bf+OVTH, bf+OVTL,
                                     D, D, D, S, SD, 0, SD, 1.f, 1, 2);

    dim3 g_sc(S / 128, S / 128, NB);
    mma_gemm<<<g_sc, thr, SMEM_DYN>>>(bf+OQH, bf+OQL, bf+OKH, bf+OKL, nullptr,
                                      scp, nullptr, nullptr,
                                      D, D, D, S, SD, SD, SSZ, 0.03125f, 0, 0);

    softmax_rows<<<NB * S, 256>>>(scp, bf + OPH, bf + OPL);

    dim3 g_o(D / 128, S / 128, NB);
    mma_gemm<<<g_o, thr, SMEM_DYN>>>(bf+OPH, bf+OPL, bf+OVTH, bf+OVTL, nullptr,
                                     out, nullptr, nullptr,
                                     S, S, S, D, SSZ, SD, SD, 1.f, 0, 0);
}